// round 17
// baseline (speedup 1.0000x reference)
#include <cuda_runtime.h>
#include <cuda_bf16.h>
#include <math.h>

#define N 8192
#define KD 32
#define STRIP 8
#define NSTRIPS (N / STRIP)     // 1024

#define MUVAL (1.0f / 8192.0f)
#define NUVAL (1.0f / 8192.0f)

// Scratch (allocation-free: device globals)
__device__ __nv_bfloat16 d_K[(size_t)N * N];        // 128 MB: K = exp(-C) bf16
__device__ float d_v[N];                             // v = exp(g)
__device__ __nv_bfloat16 d_ps[(size_t)NSTRIPS * N]; // column-sum partials, bf16 (16 MB)
__device__ float d_pt[(size_t)NSTRIPS * N];         // loss partials fp32 (final iter)

__device__ __forceinline__ unsigned tf32cvt(float v)
{
    unsigned r;
    asm("cvt.rna.tf32.f32 %0, %1;" : "=r"(r) : "f"(v));
    return r;
}

__device__ __forceinline__ void mma_tf32(
    float& d0, float& d1, float& d2, float& d3,
    unsigned a0, unsigned a1, unsigned a2, unsigned a3,
    unsigned b0, unsigned b1)
{
    asm("mma.sync.aligned.m16n8k8.row.col.f32.tf32.tf32.f32 "
        "{%0,%1,%2,%3}, {%4,%5,%6,%7}, {%8,%9}, {%0,%1,%2,%3};"
        : "+f"(d0), "+f"(d1), "+f"(d2), "+f"(d3)
        : "r"(a0), "r"(a1), "r"(a2), "r"(a3), "r"(b0), "r"(b1));
}

// unpack a uint4 of 8 bf16 into 8 floats
__device__ __forceinline__ void unpack8(const uint4& u, float* c)
{
    union { uint4 q; __nv_bfloat162 h[4]; } k;
    k.q = u;
    float2 t0 = __bfloat1622float2(k.h[0]);
    float2 t1 = __bfloat1622float2(k.h[1]);
    float2 t2 = __bfloat1622float2(k.h[2]);
    float2 t3 = __bfloat1622float2(k.h[3]);
    c[0] = t0.x; c[1] = t0.y; c[2] = t1.x; c[3] = t1.y;
    c[4] = t2.x; c[5] = t2.y; c[6] = t3.x; c[7] = t3.y;
}

// ---------------------------------------------------------------------------
// Kernel 1: build K = exp(-(|x_i|^2 + |y_j|^2 - 2 x_i.y_j)) in bf16 via
// tf32 tensor-core MMA. 128x128 tile per block, 8 warps.
// Also inits v = 1 and zeroes the output scalar.
// ---------------------------------------------------------------------------
__global__ __launch_bounds__(256) void build_k_kernel(
    const float* __restrict__ x, const float* __restrict__ y,
    float* __restrict__ out)
{
    __shared__ float xs[128][36];
    __shared__ float ys[128][36];
    __shared__ float xn[128];
    __shared__ float yn[128];

    const int tid = threadIdx.x;
    const int lane = tid & 31;
    const int w = tid >> 5;          // warp 0..7
    const int bx = blockIdx.x, by = blockIdx.y;
    const int row0 = by * 128, col0 = bx * 128;

    {
        int gid = (by * gridDim.x + bx) * 256 + tid;
        if (gid < N) d_v[gid] = 1.0f;
        if (gid == 0) out[0] = 0.0f;
    }

    const float4* x4 = (const float4*)(x + (size_t)row0 * KD);
    const float4* y4 = (const float4*)(y + (size_t)col0 * KD);
#pragma unroll
    for (int it = 0; it < 4; ++it) {
        int f = tid + it * 256;          // 0..1023
        int r = f >> 3;
        int c = (f & 7) * 4;
        float4 vx = x4[f];
        xs[r][c] = vx.x; xs[r][c + 1] = vx.y; xs[r][c + 2] = vx.z; xs[r][c + 3] = vx.w;
        float4 vy = y4[f];
        ys[r][c] = vy.x; ys[r][c + 1] = vy.y; ys[r][c + 2] = vy.z; ys[r][c + 3] = vy.w;
    }
    __syncthreads();

    if (tid < 128) {
        float s = 0.0f;
#pragma unroll
        for (int k = 0; k < KD; ++k) { float a = xs[tid][k]; s = fmaf(a, a, s); }
        xn[tid] = s;
    } else {
        int r = tid - 128;
        float s = 0.0f;
#pragma unroll
        for (int k = 0; k < KD; ++k) { float a = ys[r][k]; s = fmaf(a, a, s); }
        yn[r] = s;
    }
    __syncthreads();

    const int g = lane >> 2;         // 0..7
    const int tg = lane & 3;         // 0..3
    const int ra = 16 * w + g;       // A-frag row (local)
    const int rb = ra + 8;

    unsigned A[4][4];
#pragma unroll
    for (int k8 = 0; k8 < 4; ++k8) {
        A[k8][0] = tf32cvt(xs[ra][k8 * 8 + tg]);
        A[k8][1] = tf32cvt(xs[rb][k8 * 8 + tg]);
        A[k8][2] = tf32cvt(xs[ra][k8 * 8 + tg + 4]);
        A[k8][3] = tf32cvt(xs[rb][k8 * 8 + tg + 4]);
    }

    float acc[16][4];
#pragma unroll
    for (int n = 0; n < 16; ++n)
#pragma unroll
        for (int q = 0; q < 4; ++q) acc[n][q] = 0.0f;

#pragma unroll
    for (int n = 0; n < 16; ++n) {
        const int yr = n * 8 + g;
#pragma unroll
        for (int k8 = 0; k8 < 4; ++k8) {
            unsigned b0 = tf32cvt(ys[yr][k8 * 8 + tg]);
            unsigned b1 = tf32cvt(ys[yr][k8 * 8 + tg + 4]);
            mma_tf32(acc[n][0], acc[n][1], acc[n][2], acc[n][3],
                     A[k8][0], A[k8][1], A[k8][2], A[k8][3], b0, b1);
        }
    }

    const float xna = xn[ra];
    const float xnb = xn[rb];
    const int gra = row0 + ra;
    const int grb = row0 + rb;
#pragma unroll
    for (int n = 0; n < 16; ++n) {
        int c0 = n * 8 + 2 * tg;
        float yn0 = yn[c0], yn1 = yn[c0 + 1];
        float k00 = __expf(2.0f * acc[n][0] - xna - yn0);
        float k01 = __expf(2.0f * acc[n][1] - xna - yn1);
        float k10 = __expf(2.0f * acc[n][2] - xnb - yn0);
        float k11 = __expf(2.0f * acc[n][3] - xnb - yn1);
        *(__nv_bfloat162*)(d_K + (size_t)gra * N + col0 + c0) = __floats2bfloat162_rn(k00, k01);
        *(__nv_bfloat162*)(d_K + (size_t)grb * N + col0 + c0) = __floats2bfloat162_rn(k10, k11);
    }
}

// ---------------------------------------------------------------------------
// Kernel 2 (register-resident sweep): block owns an 8-row strip of K.
// Each thread loads its 8-row x 2-uint4-col patch into 16 uint4 REGISTERS
// (single DRAM read of K per iteration), computes row-sum contributions,
// block-reduces to u, then computes column partials from the SAME registers.
// grid NSTRIPS=1024, block 512.
// FIN: also fp32 t-partials sum_i (-log K) K u for the loss.
// ---------------------------------------------------------------------------
template <bool FIN>
__global__ __launch_bounds__(512, 1) void sweep_kernel()
{
    __shared__ float part[16][9];        // per-warp row partials (padded)
    __shared__ float us[STRIP];

    const int tid = threadIdx.x;
    const int wrp = tid >> 5;            // 0..15
    const int lane = tid & 31;
    const int i0 = blockIdx.x * STRIP;

    const uint4*  K8 = (const uint4*)d_K;   // 1024 uint4 per row
    const float4* v4 = (const float4*)d_v;

    const int ja = tid;                  // uint4-col A
    const int jb = tid + 512;            // uint4-col B

    // ---- Load K patch into registers (the only K read) ----
    uint4 ka[STRIP], kb[STRIP];
#pragma unroll
    for (int r = 0; r < STRIP; ++r) {
        ka[r] = K8[(size_t)(i0 + r) * (N / 8) + ja];
        kb[r] = K8[(size_t)(i0 + r) * (N / 8) + jb];
    }

    // v for this thread's 16 bf16 columns
    const float4 va0 = v4[2 * ja], va1 = v4[2 * ja + 1];
    const float4 vb0 = v4[2 * jb], vb1 = v4[2 * jb + 1];

    // ---- Phase 1: row-sum contributions ----
    float rs[STRIP];
#pragma unroll
    for (int r = 0; r < STRIP; ++r) {
        float c[8];
        float s = 0.0f;
        unpack8(ka[r], c);
        s = fmaf(c[0], va0.x, s); s = fmaf(c[1], va0.y, s);
        s = fmaf(c[2], va0.z, s); s = fmaf(c[3], va0.w, s);
        s = fmaf(c[4], va1.x, s); s = fmaf(c[5], va1.y, s);
        s = fmaf(c[6], va1.z, s); s = fmaf(c[7], va1.w, s);
        unpack8(kb[r], c);
        s = fmaf(c[0], vb0.x, s); s = fmaf(c[1], vb0.y, s);
        s = fmaf(c[2], vb0.z, s); s = fmaf(c[3], vb0.w, s);
        s = fmaf(c[4], vb1.x, s); s = fmaf(c[5], vb1.y, s);
        s = fmaf(c[6], vb1.z, s); s = fmaf(c[7], vb1.w, s);
        rs[r] = s;
    }
#pragma unroll
    for (int r = 0; r < STRIP; ++r)
#pragma unroll
        for (int o = 16; o > 0; o >>= 1)
            rs[r] += __shfl_xor_sync(0xffffffffu, rs[r], o);
    if (lane == 0) {
#pragma unroll
        for (int r = 0; r < STRIP; ++r) part[wrp][r] = rs[r];
    }
    __syncthreads();
    if (tid < STRIP) {
        float s = 0.0f;
#pragma unroll
        for (int w = 0; w < 16; ++w) s += part[w][tid];
        us[tid] = MUVAL / s;
    }
    __syncthreads();

    float u[STRIP];
#pragma unroll
    for (int r = 0; r < STRIP; ++r) u[r] = us[r];

    // ---- Phase 2: column partials from registers ----
    float acca[8], accb[8];
#pragma unroll
    for (int c = 0; c < 8; ++c) { acca[c] = 0.0f; accb[c] = 0.0f; }
    float taca[8], tacb[8];
    if (FIN) {
#pragma unroll
        for (int c = 0; c < 8; ++c) { taca[c] = 0.0f; tacb[c] = 0.0f; }
    }

#pragma unroll
    for (int r = 0; r < STRIP; ++r) {
        const float ur = u[r];
        float c[8];
        unpack8(ka[r], c);
#pragma unroll
        for (int j = 0; j < 8; ++j) {
            acca[j] = fmaf(c[j], ur, acca[j]);
            if (FIN) taca[j] += (c[j] > 0.0f) ? (-__logf(c[j])) * c[j] * ur : 0.0f;
        }
        unpack8(kb[r], c);
#pragma unroll
        for (int j = 0; j < 8; ++j) {
            accb[j] = fmaf(c[j], ur, accb[j]);
            if (FIN) tacb[j] += (c[j] > 0.0f) ? (-__logf(c[j])) * c[j] * ur : 0.0f;
        }
    }

    // write bf16 partials (8 cols = 1 uint4 each)
    uint4* psrow = (uint4*)(d_ps + (size_t)blockIdx.x * N);
    union { uint4 q; __nv_bfloat162 h[4]; } pa, pb;
    pa.h[0] = __floats2bfloat162_rn(acca[0], acca[1]);
    pa.h[1] = __floats2bfloat162_rn(acca[2], acca[3]);
    pa.h[2] = __floats2bfloat162_rn(acca[4], acca[5]);
    pa.h[3] = __floats2bfloat162_rn(acca[6], acca[7]);
    pb.h[0] = __floats2bfloat162_rn(accb[0], accb[1]);
    pb.h[1] = __floats2bfloat162_rn(accb[2], accb[3]);
    pb.h[2] = __floats2bfloat162_rn(accb[4], accb[5]);
    pb.h[3] = __floats2bfloat162_rn(accb[6], accb[7]);
    psrow[ja] = pa.q;
    psrow[jb] = pb.q;

    if (FIN) {
        float4* ptrow = (float4*)(d_pt + (size_t)blockIdx.x * N);
        float4 q;
        q.x = taca[0]; q.y = taca[1]; q.z = taca[2]; q.w = taca[3];
        ptrow[2 * ja] = q;
        q.x = taca[4]; q.y = taca[5]; q.z = taca[6]; q.w = taca[7];
        ptrow[2 * ja + 1] = q;
        q.x = tacb[0]; q.y = tacb[1]; q.z = tacb[2]; q.w = tacb[3];
        ptrow[2 * jb] = q;
        q.x = tacb[4]; q.y = tacb[5]; q.z = tacb[6]; q.w = tacb[7];
        ptrow[2 * jb + 1] = q;
    }
}

// ---------------------------------------------------------------------------
// Kernel 3: combine 1024 bf16 strip partials -> v_j = NU / colsum_j.
// Thread (g, cl) sums 128 strips for bf162-column j2; 8 groups, smem reduce.
// grid 128, block 256 (32 bf162-cols = 64 fp columns per block).
// ---------------------------------------------------------------------------
__global__ __launch_bounds__(256) void v_combine_kernel()
{
    __shared__ float2 sm[8][32];
    const int tid = threadIdx.x;
    const int cl = tid & 31;
    const int g = tid >> 5;                      // 0..7
    const int j2 = blockIdx.x * 32 + cl;         // bf162 column

    const __nv_bfloat162* ps2 = (const __nv_bfloat162*)d_ps;
    float2 s = make_float2(0.0f, 0.0f);
#pragma unroll 8
    for (int k = 0; k < 128; ++k) {
        float2 p = __bfloat1622float2(ps2[(size_t)(g * 128 + k) * (N / 2) + j2]);
        s.x += p.x; s.y += p.y;
    }
    sm[g][cl] = s;
    __syncthreads();
    if (tid < 32) {
        float2 tot = make_float2(0.0f, 0.0f);
#pragma unroll
        for (int q = 0; q < 8; ++q) { tot.x += sm[q][tid].x; tot.y += sm[q][tid].y; }
        float2* vo = (float2*)d_v;
        float2 o; o.x = NUVAL / tot.x; o.y = NUVAL / tot.y;
        vo[blockIdx.x * 32 + tid] = o;
    }
}

// Final combine: also loss = sum_j v_j * t_j.
__global__ __launch_bounds__(256) void v_combine_final_kernel(float* __restrict__ out)
{
    __shared__ float2 sm[8][32];
    __shared__ float2 smt[8][32];
    const int tid = threadIdx.x;
    const int cl = tid & 31;
    const int g = tid >> 5;
    const int j2 = blockIdx.x * 32 + cl;

    const __nv_bfloat162* ps2 = (const __nv_bfloat162*)d_ps;
    const float2* pt2 = (const float2*)d_pt;
    float2 s = make_float2(0.0f, 0.0f);
    float2 t = make_float2(0.0f, 0.0f);
#pragma unroll 8
    for (int k = 0; k < 128; ++k) {
        size_t idx = (size_t)(g * 128 + k) * (N / 2) + j2;
        float2 p = __bfloat1622float2(ps2[idx]);
        s.x += p.x; s.y += p.y;
        float2 q = pt2[idx];
        t.x += q.x; t.y += q.y;
    }
    sm[g][cl] = s;
    smt[g][cl] = t;
    __syncthreads();
    if (tid < 32) {
        float2 tot = make_float2(0.0f, 0.0f);
        float2 tt = make_float2(0.0f, 0.0f);
#pragma unroll
        for (int q = 0; q < 8; ++q) {
            tot.x += sm[q][tid].x; tot.y += sm[q][tid].y;
            tt.x += smt[q][tid].x; tt.y += smt[q][tid].y;
        }
        float lp = (NUVAL / tot.x) * tt.x + (NUVAL / tot.y) * tt.y;
#pragma unroll
        for (int o = 16; o > 0; o >>= 1) lp += __shfl_xor_sync(0xffffffffu, lp, o);
        if (tid == 0) atomicAdd(out, lp);
    }
}

// ---------------------------------------------------------------------------
extern "C" void kernel_launch(void* const* d_in, const int* in_sizes, int n_in,
                              void* d_out, int out_size)
{
    const float* x = (const float*)d_in[0];
    const float* y = (const float*)d_in[1];
    float* out = (float*)d_out;

    build_k_kernel<<<dim3(64, 64), 256>>>(x, y, out);

    for (int t = 0; t < 10; ++t) {
        if (t < 9) {
            sweep_kernel<false><<<NSTRIPS, 512>>>();
            v_combine_kernel<<<128, 256>>>();
        } else {
            sweep_kernel<true><<<NSTRIPS, 512>>>();
            v_combine_final_kernel<<<128, 256>>>(out);
        }
    }
}